// round 6
// baseline (speedup 1.0000x reference)
#include <cuda_runtime.h>
#include <math.h>
#include <stdint.h>

// Problem constants (fixed by the reference)
#define NN 8192
#define KK 16
#define GAMMA_MIN 0.9f
#define GAMMA_MAX 0.9995f

#define ROWS_PER_BLOCK 16
#define THREADS 256
#define N4 (NN / 4)            // 2048 float4 per row
#define NBUF 4                 // in-flight TMA store buffers
#define SEG_BYTES (THREADS * 16)   // 4096 B contiguous per row segment

__device__ __forceinline__ uint32_t smem_u32(const void* p) {
    uint32_t a;
    asm("{ .reg .u64 t; cvta.to.shared.u64 t, %1; cvt.u32.u64 %0, t; }"
        : "=r"(a) : "l"(p));
    return a;
}

// ---------------------------------------------------------------------------
// Fused kernel, TMA-store epilogue.
//   Phase A: gammas + per-row nonzero compaction (general: nnz in [0,16]).
//   Phase B: per row — compute 4KB segment into smem, elected thread issues
//            cp.async.bulk (SMEM->GMEM, 4KB burst), 4 buffers pipelined.
// ---------------------------------------------------------------------------
__global__ __launch_bounds__(THREADS)
void wslow_tma_kernel(const float* __restrict__ eta,
                      const float* __restrict__ v,
                      const float* __restrict__ u,
                      float* __restrict__ out) {
    const int m4 = blockIdx.x * THREADS + threadIdx.x;   // float4 column index
    const int n0 = blockIdx.y * ROWS_PER_BLOCK;
    const int t  = threadIdx.x;

    __shared__ float4 s_buf[NBUF][THREADS];              // 16 KB staging
    __shared__ float  s_gam[KK];
    __shared__ int    s_nnz[ROWS_PER_BLOCK];
    __shared__ int    s_k[ROWS_PER_BLOCK][KK];
    __shared__ float  s_c[ROWS_PER_BLOCK][KK];

    // --- Phase A1: gammas ---
    if (t < KK) {
        float e = eta[t];
        float s = 1.0f / (1.0f + expf(-e));
        s_gam[t] = GAMMA_MIN + (GAMMA_MAX - GAMMA_MIN) * s;
    }
    __syncthreads();

    // --- Phase A2: per-row compaction ---
    if (t < ROWS_PER_BLOCK) {
        const int n = n0 + t;
        int cnt = 0;
#pragma unroll
        for (int k = 0; k < KK; k++) {
            float c = s_gam[k] * v[k * NN + n];
            if (c != 0.0f) { s_k[t][cnt] = k; s_c[t][cnt] = c; cnt++; }
        }
        s_nnz[t] = cnt;
    }
    __syncthreads();

    // --- Phase B ---
    const float4* __restrict__ u4 = reinterpret_cast<const float4*>(u);
    float* gdst = out + (size_t)n0 * NN + (size_t)blockIdx.x * (SEG_BYTES / 4);

    int    kprev = -1;
    float4 uv    = make_float4(0.f, 0.f, 0.f, 0.f);

    for (int r = 0; r < ROWS_PER_BLOCK; r++) {
        const int buf = r & (NBUF - 1);

        // Make sure this buffer's previous bulk store has read out of smem.
        if (r >= NBUF) {
            if (t == 0)
                asm volatile("cp.async.bulk.wait_group.read %0;" :: "n"(NBUF - 1) : "memory");
            __syncthreads();
        }

        // Compute this row's segment.
        float4 acc = make_float4(0.f, 0.f, 0.f, 0.f);
        const int nn = s_nnz[r];
        for (int i = 0; i < nn; i++) {
            const int k = s_k[r][i];
            if (k != kprev) {                 // block-uniform branch
                uv = __ldg(&u4[k * N4 + m4]);
                kprev = k;
            }
            const float c = s_c[r][i];
            acc.x = fmaf(c, uv.x, acc.x);
            acc.y = fmaf(c, uv.y, acc.y);
            acc.z = fmaf(c, uv.z, acc.z);
            acc.w = fmaf(c, uv.w, acc.w);
        }
        s_buf[buf][t] = acc;
        __syncthreads();                      // all STS visible, then fence+issue

        if (t == 0) {
            asm volatile("fence.proxy.async.shared::cta;" ::: "memory");
            asm volatile(
                "cp.async.bulk.global.shared::cta.bulk_group [%0], [%1], %2;"
                :: "l"(gdst + (size_t)r * NN),
                   "r"(smem_u32(&s_buf[buf][0])),
                   "r"((uint32_t)SEG_BYTES)
                : "memory");
            asm volatile("cp.async.bulk.commit_group;" ::: "memory");
        }
    }

    // Drain all outstanding bulk stores before exit.
    if (t == 0)
        asm volatile("cp.async.bulk.wait_group.read 0;" ::: "memory");
}

// ---------------------------------------------------------------------------
extern "C" void kernel_launch(void* const* d_in, const int* in_sizes, int n_in,
                              void* d_out, int out_size) {
    const float* eta = (const float*)d_in[0];   // [16]
    const float* v   = (const float*)d_in[1];   // [16, 8192]
    const float* u   = (const float*)d_in[2];   // [16, 8192]
    float* out = (float*)d_out;                 // [8192, 8192] fp32

    dim3 grid(NN * 4 / SEG_BYTES, NN / ROWS_PER_BLOCK);   // (8, 512) = 4096
    wslow_tma_kernel<<<grid, THREADS>>>(eta, v, u, out);
}

// round 7
// speedup vs baseline: 1.0163x; 1.0163x over previous
#include <cuda_runtime.h>
#include <math.h>

// Problem constants (fixed by the reference)
#define NN 8192
#define KK 16
#define GAMMA_MIN 0.9f
#define GAMMA_MAX 0.9995f

#define ROWS_PER_BLOCK 16
#define THREADS 256
#define N4 (NN / 4)            // 2048 float4 per row

// ---------------------------------------------------------------------------
// Fused single kernel (R4 structure, 32 regs, 8 blocks/SM). ONLY change vs
// R4 (best, 43.1us): __stcs -> __stwt (write-through). Zero dirty-L2 tail;
// DRAM scheduler sees the full write stream immediately.
//   Phase A: gammas + per-row nonzero compaction of c[k] = gamma_k * v[k][n]
//            (general: handles any nnz in [0,16]).
//   Phase B: W[n][m] = sum_i c_i * u[k_i][m]; register-cached u vector,
//            128-bit write-through stores.
// ---------------------------------------------------------------------------
__global__ __launch_bounds__(THREADS)
void wslow_fused_kernel(const float* __restrict__ eta,
                        const float* __restrict__ v,
                        const float* __restrict__ u,
                        float* __restrict__ out) {
    const int m4 = blockIdx.x * THREADS + threadIdx.x;   // float4 column index
    const int n0 = blockIdx.y * ROWS_PER_BLOCK;          // first row of tile
    const int t  = threadIdx.x;

    __shared__ float s_gam[KK];
    __shared__ int   s_nnz[ROWS_PER_BLOCK];
    __shared__ int   s_k[ROWS_PER_BLOCK][KK];
    __shared__ float s_c[ROWS_PER_BLOCK][KK];

    // --- Phase A1: gammas (16 threads) ---
    if (t < KK) {
        float e = eta[t];
        float s = 1.0f / (1.0f + expf(-e));
        s_gam[t] = GAMMA_MIN + (GAMMA_MAX - GAMMA_MIN) * s;
    }
    __syncthreads();

    // --- Phase A2: per-row compaction (one thread per row) ---
    if (t < ROWS_PER_BLOCK) {
        const int n = n0 + t;
        int cnt = 0;
#pragma unroll
        for (int k = 0; k < KK; k++) {
            float c = s_gam[k] * v[k * NN + n];
            if (c != 0.0f) {
                s_k[t][cnt] = k;
                s_c[t][cnt] = c;
                cnt++;
            }
        }
        s_nnz[t] = cnt;
    }
    __syncthreads();

    // --- Phase B: streamed outer-product accumulation ---
    const float4* __restrict__ u4 = reinterpret_cast<const float4*>(u);
    float4* __restrict__ o4 = reinterpret_cast<float4*>(out) + (size_t)n0 * N4 + m4;

    int    kprev = -1;
    float4 uv    = make_float4(0.f, 0.f, 0.f, 0.f);

#pragma unroll 8
    for (int r = 0; r < ROWS_PER_BLOCK; r++) {
        float4 acc = make_float4(0.f, 0.f, 0.f, 0.f);
        const int nn = s_nnz[r];
        for (int i = 0; i < nn; i++) {
            const int k = s_k[r][i];
            if (k != kprev) {                 // block-uniform branch
                uv = __ldg(&u4[k * N4 + m4]); // L1/L2-resident
                kprev = k;
            }
            const float c = s_c[r][i];
            acc.x = fmaf(c, uv.x, acc.x);
            acc.y = fmaf(c, uv.y, acc.y);
            acc.z = fmaf(c, uv.z, acc.z);
            acc.w = fmaf(c, uv.w, acc.w);
        }
        __stwt(o4, acc);                      // write-through 128-bit store
        o4 += N4;
    }
}

// ---------------------------------------------------------------------------
extern "C" void kernel_launch(void* const* d_in, const int* in_sizes, int n_in,
                              void* d_out, int out_size) {
    const float* eta = (const float*)d_in[0];   // [16]
    const float* v   = (const float*)d_in[1];   // [16, 8192]
    const float* u   = (const float*)d_in[2];   // [16, 8192]
    float* out = (float*)d_out;                 // [8192, 8192] fp32

    dim3 grid(N4 / THREADS, NN / ROWS_PER_BLOCK);   // (8, 512) = 4096 blocks
    wslow_fused_kernel<<<grid, THREADS>>>(eta, v, u, out);
}

// round 8
// speedup vs baseline: 1.1377x; 1.1195x over previous
#include <cuda_runtime.h>
#include <math.h>

// Problem constants (fixed by the reference)
#define NN 8192
#define KK 16
#define GAMMA_MIN 0.9f
#define GAMMA_MAX 0.9995f

#define ROWS_PER_BLOCK 8       // R8: 16 -> 8 (continue measured trend 32->16 = -0.4us)
#define THREADS 256
#define N4 (NN / 4)            // 2048 float4 per row

// ---------------------------------------------------------------------------
// Fused single kernel (R4 structure, __stcs stores — the proven-best policy).
//   Phase A: gammas + per-row nonzero compaction of c[k] = gamma_k * v[k][n]
//            (general: handles any nnz in [0,16]).
//   Phase B: W[n][m] = sum_i c_i * u[k_i][m]; register-cached u vector,
//            128-bit streaming stores.
// ---------------------------------------------------------------------------
__global__ __launch_bounds__(THREADS)
void wslow_fused_kernel(const float* __restrict__ eta,
                        const float* __restrict__ v,
                        const float* __restrict__ u,
                        float* __restrict__ out) {
    const int m4 = blockIdx.x * THREADS + threadIdx.x;   // float4 column index
    const int n0 = blockIdx.y * ROWS_PER_BLOCK;          // first row of tile
    const int t  = threadIdx.x;

    __shared__ float s_gam[KK];
    __shared__ int   s_nnz[ROWS_PER_BLOCK];
    __shared__ int   s_k[ROWS_PER_BLOCK][KK];
    __shared__ float s_c[ROWS_PER_BLOCK][KK];

    // --- Phase A1: gammas (16 threads) ---
    if (t < KK) {
        float e = eta[t];
        float s = 1.0f / (1.0f + expf(-e));
        s_gam[t] = GAMMA_MIN + (GAMMA_MAX - GAMMA_MIN) * s;
    }
    __syncthreads();

    // --- Phase A2: per-row compaction (one thread per row) ---
    if (t < ROWS_PER_BLOCK) {
        const int n = n0 + t;
        int cnt = 0;
#pragma unroll
        for (int k = 0; k < KK; k++) {
            float c = s_gam[k] * v[k * NN + n];
            if (c != 0.0f) {
                s_k[t][cnt] = k;
                s_c[t][cnt] = c;
                cnt++;
            }
        }
        s_nnz[t] = cnt;
    }
    __syncthreads();

    // --- Phase B: streamed outer-product accumulation ---
    const float4* __restrict__ u4 = reinterpret_cast<const float4*>(u);
    float4* __restrict__ o4 = reinterpret_cast<float4*>(out) + (size_t)n0 * N4 + m4;

    int    kprev = -1;
    float4 uv    = make_float4(0.f, 0.f, 0.f, 0.f);

#pragma unroll
    for (int r = 0; r < ROWS_PER_BLOCK; r++) {
        float4 acc = make_float4(0.f, 0.f, 0.f, 0.f);
        const int nn = s_nnz[r];
        for (int i = 0; i < nn; i++) {
            const int k = s_k[r][i];
            if (k != kprev) {                 // block-uniform branch
                uv = __ldg(&u4[k * N4 + m4]); // L1/L2-resident
                kprev = k;
            }
            const float c = s_c[r][i];
            acc.x = fmaf(c, uv.x, acc.x);
            acc.y = fmaf(c, uv.y, acc.y);
            acc.z = fmaf(c, uv.z, acc.z);
            acc.w = fmaf(c, uv.w, acc.w);
        }
        __stcs(o4, acc);                      // streaming 128-bit store (proven best)
        o4 += N4;
    }
}

// ---------------------------------------------------------------------------
extern "C" void kernel_launch(void* const* d_in, const int* in_sizes, int n_in,
                              void* d_out, int out_size) {
    const float* eta = (const float*)d_in[0];   // [16]
    const float* v   = (const float*)d_in[1];   // [16, 8192]
    const float* u   = (const float*)d_in[2];   // [16, 8192]
    float* out = (float*)d_out;                 // [8192, 8192] fp32

    dim3 grid(N4 / THREADS, NN / ROWS_PER_BLOCK);   // (8, 1024) = 8192 blocks
    wslow_fused_kernel<<<grid, THREADS>>>(eta, v, u, out);
}